// round 7
// baseline (speedup 1.0000x reference)
#include <cuda_runtime.h>
#include <cuda_bf16.h>
#include <cstdint>

// Sobel conv (cross-correlation, SAME zero padding) + sign-difference maps.
// Rolling-register design (OPT=4), no smem, no barriers.
// Register-dieted: single output base pointer + uint32 element offsets,
// __launch_bounds__(256,5) targets <=51 regs -> 62.5% occupancy.

#define IMG_W 1024
#define IMG_H 1024
#define RS 16            // output rows per warp
#define NWARP 8          // warps per block
#define NT (NWARP * 32)

__device__ __forceinline__ float fsign(float v) {
    return (float)((v > 0.0f) - (v < 0.0f));
}

__global__ __launch_bounds__(NT, 5)
void sobel_sign_kernel(const float* __restrict__ x,
                       float* __restrict__ out,
                       unsigned y0base, unsigned y1base) {
    const int lane = threadIdx.x & 31;
    const int wid  = threadIdx.x >> 5;
    const int b    = blockIdx.z;
    const int w0   = blockIdx.x * 128;                  // strip base col
    const int r0   = (blockIdx.y * NWARP + wid) * RS;   // first output row
    const int wb   = w0 + lane * 4;                     // lane base col

    // uint32 element offsets (all buffers < 1G elements)
    const unsigned xoff   = (unsigned)b * (IMG_H * IMG_W) + wb;
    const unsigned yxoff  = (unsigned)b * (2 * IMG_H * IMG_W) + wb;
    const unsigned yyoff  = yxoff + IMG_H * IMG_W;
    const unsigned eoff   = (unsigned)b * ((IMG_H - 1) * (IMG_W - 1)) + wb;

    const bool lane0   = (lane == 0);
    const bool lane31  = (lane == 31);
    const bool has_l   = (w0 > 0);
    const bool has_r   = (w0 + 128 < IMG_W);
    const bool lastcol = (wb + 4 >= IMG_W);   // last lane of last strip

    // rolling state: horizontal diffs (5-wide, incl. col wb+4) and sums (4-wide)
    float hdP1[5] = {0,0,0,0,0}, hdP2[5] = {0,0,0,0,0};
    float hsP1[4] = {0,0,0,0},   hsP2[4] = {0,0,0,0};
    float sgyP[4] = {0,0,0,0};

    #pragma unroll
    for (int i = 0; i < RS + 3; i++) {
        const int j = r0 - 1 + i;                 // input row for this step

        float4 v = make_float4(0.f, 0.f, 0.f, 0.f);
        float lf = 0.f, rt1 = 0.f, rt2 = 0.f;
        if ((unsigned)j < (unsigned)IMG_H) {
            const unsigned ro = xoff + (unsigned)j * IMG_W;
            v = *reinterpret_cast<const float4*>(x + ro);
            if (lane0 && has_l)
                lf = x[ro - (unsigned)(lane * 4) - 1u];
            if (lane31 && has_r) {
                const float2 t2 = *reinterpret_cast<const float2*>(x + ro + 4u);
                rt1 = t2.x; rt2 = t2.y;
            }
        }
        // column halo via shuffles
        float left = __shfl_up_sync(0xffffffffu, v.w, 1);
        float rr1  = __shfl_down_sync(0xffffffffu, v.x, 1);
        float rr2  = __shfl_down_sync(0xffffffffu, v.y, 1);
        if (lane0)  left = lf;
        if (lane31) { rr1 = rt1; rr2 = rt2; }

        // horizontal combos for row j
        float hd[5], hs[4];
        hd[0] = left - v.y;  hd[1] = v.x - v.z;  hd[2] = v.y - v.w;
        hd[3] = v.z - rr1;   hd[4] = v.w - rr2;
        hs[0] = fmaf(2.f, v.x, left + v.y);
        hs[1] = fmaf(2.f, v.y, v.x + v.z);
        hs[2] = fmaf(2.f, v.z, v.y + v.w);
        hs[3] = fmaf(2.f, v.w, v.z + rr1);

        if (i >= 2) {
            const int m = r0 + i - 2;             // gx/gy now complete for row m
            float gy[4], sgy[4];
            #pragma unroll
            for (int k = 0; k < 4; k++) {
                gy[k]  = hsP2[k] - hs[k];
                sgy[k] = fsign(gy[k]);
            }

            if (i <= RS + 1) {                    // emit y + y0 for rows r0..r0+15
                float gx[5], sx[5];
                #pragma unroll
                for (int k = 0; k < 5; k++)
                    gx[k] = fmaf(2.f, hdP1[k], hdP2[k] + hd[k]);
                #pragma unroll
                for (int k = 0; k < 5; k++) sx[k] = fsign(gx[k]);

                *reinterpret_cast<float4*>(out + yxoff + (unsigned)m * IMG_W) =
                    make_float4(gx[0], gx[1], gx[2], gx[3]);
                *reinterpret_cast<float4*>(out + yyoff + (unsigned)m * IMG_W) =
                    make_float4(gy[0], gy[1], gy[2], gy[3]);

                if (m < IMG_H - 1) {
                    const unsigned o = y0base + eoff + (unsigned)m * (IMG_W - 1);
                    out[o + 0] = sx[0] - sx[1];
                    out[o + 1] = sx[1] - sx[2];
                    out[o + 2] = sx[2] - sx[3];
                    if (!lastcol) out[o + 3] = sx[3] - sx[4];
                }
            }
            if (i >= 3) {
                const int m1 = r0 + i - 3;        // y1 row m1 needs sgy[m1], sgy[m1+1]
                if (m1 < IMG_H - 1) {
                    const unsigned o = y1base + eoff + (unsigned)m1 * (IMG_W - 1);
                    out[o + 0] = sgyP[0] - sgy[0];
                    out[o + 1] = sgyP[1] - sgy[1];
                    out[o + 2] = sgyP[2] - sgy[2];
                    if (!lastcol) out[o + 3] = sgyP[3] - sgy[3];
                }
            }
            #pragma unroll
            for (int k = 0; k < 4; k++) sgyP[k] = sgy[k];
        }
        // rotate window
        #pragma unroll
        for (int k = 0; k < 5; k++) { hdP2[k] = hdP1[k]; hdP1[k] = hd[k]; }
        #pragma unroll
        for (int k = 0; k < 4; k++) { hsP2[k] = hsP1[k]; hsP1[k] = hs[k]; }
    }
}

extern "C" void kernel_launch(void* const* d_in, const int* in_sizes, int n_in,
                              void* d_out, int out_size) {
    const float* x = (const float*)d_in[0];
    const int B = in_sizes[0] / (IMG_H * IMG_W);

    float* out = (float*)d_out;
    const unsigned y0base = (unsigned)B * 2u * IMG_H * IMG_W;
    const unsigned y1base = y0base + (unsigned)B * (IMG_H - 1) * (IMG_W - 1);

    dim3 block(NT, 1, 1);
    dim3 grid(IMG_W / 128, IMG_H / (RS * NWARP), B);
    sobel_sign_kernel<<<grid, block>>>(x, out, y0base, y1base);
}

// round 8
// speedup vs baseline: 1.4893x; 1.4893x over previous
#include <cuda_runtime.h>
#include <cuda_bf16.h>
#include <cstdint>

// Sobel conv (cross-correlation, SAME zero padding) + sign-difference maps.
// Rolling-register design, STRIDED column ownership: lane k owns cols
// {w0+k, w0+32+k, w0+64+k, w0+96+k} so every LDG/STG (x, y, y0, y1) is
// warp-coalesced. No smem, no barriers. Column halo via shuffles.

#define IMG_W 1024
#define IMG_H 1024
#define RS 16            // output rows per warp
#define NWARP 8          // warps per block
#define NT (NWARP * 32)
#define FULL 0xffffffffu

__device__ __forceinline__ float fsign(float v) {
    return (float)((v > 0.0f) - (v < 0.0f));
}

__global__ __launch_bounds__(NT, 4)
void sobel_sign_kernel(const float* __restrict__ x,
                       float* __restrict__ y,
                       float* __restrict__ y0,
                       float* __restrict__ y1) {
    const int lane = threadIdx.x & 31;
    const int wid  = threadIdx.x >> 5;
    const int b    = blockIdx.z;
    const int w0   = blockIdx.x * 128;                  // strip base col
    const int r0   = (blockIdx.y * NWARP + wid) * RS;   // first output row
    const int col  = w0 + lane;                         // sub-block 0 col

    const float* __restrict__ xb = x + (size_t)b * IMG_H * IMG_W + col;
    float* __restrict__ ybx = y + (size_t)b * 2 * IMG_H * IMG_W + col;
    float* __restrict__ yby = ybx + (size_t)IMG_H * IMG_W;
    float* __restrict__ y0b = y0 + (size_t)b * (IMG_H - 1) * (IMG_W - 1) + col;
    float* __restrict__ y1b = y1 + (size_t)b * (IMG_H - 1) * (IMG_W - 1) + col;

    const bool lane0  = (lane == 0);
    const bool lane31 = (lane == 31);
    const bool has_l  = (w0 > 0);
    const bool has_r  = (w0 + 128 < IMG_W);
    const bool skip3  = lane31 && !has_r;   // col w0+127 == 1023 on last strip

    // rolling 3-row windows per owned col (4 sub-blocks) + strip-right col
    float hdP1[4] = {0,0,0,0}, hdP2[4] = {0,0,0,0};
    float hsP1[4] = {0,0,0,0}, hsP2[4] = {0,0,0,0};
    float hdRP1 = 0.f, hdRP2 = 0.f;
    float sgyP[4] = {0,0,0,0};

    #pragma unroll
    for (int i = 0; i < RS + 3; i++) {
        const int j = r0 - 1 + i;                 // input row for this step

        float vs0 = 0.f, vs1 = 0.f, vs2 = 0.f, vs3 = 0.f;
        float lf = 0.f, rt1 = 0.f, rt2 = 0.f;
        if ((unsigned)j < (unsigned)IMG_H) {
            const float* row = xb + (size_t)j * IMG_W;
            vs0 = row[0];
            vs1 = row[32];
            vs2 = row[64];
            vs3 = row[96];
            if (lane0 && has_l) lf = row[-1];
            if (lane31 && has_r) {
                const float2 t2 = *reinterpret_cast<const float2*>(row + (128 - 31));
                rt1 = t2.x; rt2 = t2.y;
            }
        }

        // left/right neighbors for each sub-block via shuffles + patches
        float l0 = __shfl_up_sync(FULL, vs0, 1);
        float l1 = __shfl_up_sync(FULL, vs1, 1);
        float l2 = __shfl_up_sync(FULL, vs2, 1);
        float l3 = __shfl_up_sync(FULL, vs3, 1);
        float r_0 = __shfl_down_sync(FULL, vs0, 1);
        float r_1 = __shfl_down_sync(FULL, vs1, 1);
        float r_2 = __shfl_down_sync(FULL, vs2, 1);
        float r_3 = __shfl_down_sync(FULL, vs3, 1);
        const float t0 = __shfl_sync(FULL, vs0, 31);  // top of sub-block 0
        const float t1 = __shfl_sync(FULL, vs1, 31);
        const float t2v = __shfl_sync(FULL, vs2, 31);
        const float b1 = __shfl_sync(FULL, vs1, 0);   // bottom of sub-block 1
        const float b2 = __shfl_sync(FULL, vs2, 0);
        const float b3 = __shfl_sync(FULL, vs3, 0);
        if (lane0)  { l0 = lf; l1 = t0; l2 = t1; l3 = t2v; }
        if (lane31) { r_0 = b1; r_1 = b2; r_2 = b3; r_3 = rt1; }

        float hd[4], hs[4];
        hd[0] = l0 - r_0;  hd[1] = l1 - r_1;
        hd[2] = l2 - r_2;  hd[3] = l3 - r_3;
        hs[0] = fmaf(2.f, vs0, l0 + r_0);
        hs[1] = fmaf(2.f, vs1, l1 + r_1);
        hs[2] = fmaf(2.f, vs2, l2 + r_2);
        hs[3] = fmaf(2.f, vs3, l3 + r_3);
        const float hdR = vs3 - rt2;              // col w0+128 (lane31 only valid)

        if (i >= 2) {
            const int m = r0 + i - 2;             // gx/gy complete for row m
            float gy[4], sgy[4];
            #pragma unroll
            for (int k = 0; k < 4; k++) {
                gy[k]  = hsP2[k] - hs[k];
                sgy[k] = fsign(gy[k]);
            }

            if (i <= RS + 1) {                    // emit y + y0 for rows r0..r0+RS-1
                float gx[4], sgx[4];
                #pragma unroll
                for (int k = 0; k < 4; k++) {
                    gx[k]  = fmaf(2.f, hdP1[k], hdP2[k] + hd[k]);
                    sgx[k] = fsign(gx[k]);
                }
                const float gxR = fmaf(2.f, hdRP1, hdRP2 + hdR);

                const unsigned ro = (unsigned)m * IMG_W;
                ybx[ro +  0] = gx[0];  ybx[ro + 32] = gx[1];
                ybx[ro + 64] = gx[2];  ybx[ro + 96] = gx[3];
                yby[ro +  0] = gy[0];  yby[ro + 32] = gy[1];
                yby[ro + 64] = gy[2];  yby[ro + 96] = gy[3];

                // neighbor signs for y0
                float sxn0 = __shfl_down_sync(FULL, sgx[0], 1);
                float sxn1 = __shfl_down_sync(FULL, sgx[1], 1);
                float sxn2 = __shfl_down_sync(FULL, sgx[2], 1);
                float sxn3 = __shfl_down_sync(FULL, sgx[3], 1);
                const float nb0 = __shfl_sync(FULL, sgx[1], 0);
                const float nb1 = __shfl_sync(FULL, sgx[2], 0);
                const float nb2 = __shfl_sync(FULL, sgx[3], 0);
                if (lane31) { sxn0 = nb0; sxn1 = nb1; sxn2 = nb2; sxn3 = fsign(gxR); }

                if (m < IMG_H - 1) {
                    const unsigned eo = (unsigned)m * (IMG_W - 1);
                    y0b[eo +  0] = sgx[0] - sxn0;
                    y0b[eo + 32] = sgx[1] - sxn1;
                    y0b[eo + 64] = sgx[2] - sxn2;
                    if (!skip3) y0b[eo + 96] = sgx[3] - sxn3;
                }
            }
            if (i >= 3) {
                const int m1 = r0 + i - 3;        // y1 row m1 needs sgy[m1], sgy[m1+1]
                if (m1 < IMG_H - 1) {
                    const unsigned eo = (unsigned)m1 * (IMG_W - 1);
                    y1b[eo +  0] = sgyP[0] - sgy[0];
                    y1b[eo + 32] = sgyP[1] - sgy[1];
                    y1b[eo + 64] = sgyP[2] - sgy[2];
                    if (!skip3) y1b[eo + 96] = sgyP[3] - sgy[3];
                }
            }
            #pragma unroll
            for (int k = 0; k < 4; k++) sgyP[k] = sgy[k];
        }
        // rotate windows
        #pragma unroll
        for (int k = 0; k < 4; k++) {
            hdP2[k] = hdP1[k]; hdP1[k] = hd[k];
            hsP2[k] = hsP1[k]; hsP1[k] = hs[k];
        }
        hdRP2 = hdRP1; hdRP1 = hdR;
    }
}

extern "C" void kernel_launch(void* const* d_in, const int* in_sizes, int n_in,
                              void* d_out, int out_size) {
    const float* x = (const float*)d_in[0];
    const int B = in_sizes[0] / (IMG_H * IMG_W);

    float* y  = (float*)d_out;
    float* y0 = y  + (size_t)B * 2 * IMG_H * IMG_W;
    float* y1 = y0 + (size_t)B * (IMG_H - 1) * (IMG_W - 1);

    dim3 block(NT, 1, 1);
    dim3 grid(IMG_W / 128, IMG_H / (RS * NWARP), B);
    sobel_sign_kernel<<<grid, block>>>(x, y, y0, y1);
}

// round 10
// speedup vs baseline: 1.6539x; 1.1105x over previous
#include <cuda_runtime.h>
#include <cuda_bf16.h>
#include <cstdint>

// Sobel conv (cross-correlation, SAME zero padding) + sign-difference maps.
// Rolling-register, STRIDED column ownership (lane k owns cols w0+{k,32+k,64+k,96+k}):
// every LDG/STG warp-coalesced. No smem, no barriers.
// RS=32 rows/warp (halo amp 35/32), single-wave grid, partial unroll for I$.

#define IMG_W 1024
#define IMG_H 1024
#define RS 32            // output rows per warp
#define NWARP 8          // warps per block
#define NT (NWARP * 32)
#define FULL 0xffffffffu

__device__ __forceinline__ float fsign(float v) {
    // +-1 with v's sign bit, zeroed when v==0 (handles -0). No NaNs in data.
    const float s = __uint_as_float((__float_as_uint(v) & 0x80000000u) | 0x3f800000u);
    return (v != 0.0f) ? s : 0.0f;
}

struct RowVals {
    float vs0, vs1, vs2, vs3, lf, rt1, rt2;
};

__device__ __forceinline__ RowVals load_row(const float* __restrict__ xb, int j,
                                            bool lane0, bool lane31,
                                            bool has_l, bool has_r) {
    RowVals r = {0.f, 0.f, 0.f, 0.f, 0.f, 0.f, 0.f};
    if ((unsigned)j < (unsigned)IMG_H) {
        const float* row = xb + (size_t)j * IMG_W;
        r.vs0 = row[0];
        r.vs1 = row[32];
        r.vs2 = row[64];
        r.vs3 = row[96];
        if (lane0 && has_l) r.lf = row[-1];
        if (lane31 && has_r) {
            const float2 t2 = *reinterpret_cast<const float2*>(row + (128 - 31));
            r.rt1 = t2.x; r.rt2 = t2.y;
        }
    }
    return r;
}

// horizontal combos for one input row (shuffle halo + sub-block patches)
__device__ __forceinline__ void row_combos(const RowVals& rv, bool lane0, bool lane31,
                                           float hd[4], float hs[4], float& hdR) {
    float l0 = __shfl_up_sync(FULL, rv.vs0, 1);
    float l1 = __shfl_up_sync(FULL, rv.vs1, 1);
    float l2 = __shfl_up_sync(FULL, rv.vs2, 1);
    float l3 = __shfl_up_sync(FULL, rv.vs3, 1);
    float r_0 = __shfl_down_sync(FULL, rv.vs0, 1);
    float r_1 = __shfl_down_sync(FULL, rv.vs1, 1);
    float r_2 = __shfl_down_sync(FULL, rv.vs2, 1);
    float r_3 = __shfl_down_sync(FULL, rv.vs3, 1);
    const float t0  = __shfl_sync(FULL, rv.vs0, 31);  // last col of sub-block 0
    const float t1  = __shfl_sync(FULL, rv.vs1, 31);
    const float t2v = __shfl_sync(FULL, rv.vs2, 31);
    const float b1  = __shfl_sync(FULL, rv.vs1, 0);   // first col of sub-block 1
    const float b2  = __shfl_sync(FULL, rv.vs2, 0);
    const float b3  = __shfl_sync(FULL, rv.vs3, 0);
    if (lane0)  { l0 = rv.lf; l1 = t0; l2 = t1; l3 = t2v; }
    if (lane31) { r_0 = b1; r_1 = b2; r_2 = b3; r_3 = rv.rt1; }
    hd[0] = l0 - r_0;  hd[1] = l1 - r_1;
    hd[2] = l2 - r_2;  hd[3] = l3 - r_3;
    hs[0] = fmaf(2.f, rv.vs0, l0 + r_0);
    hs[1] = fmaf(2.f, rv.vs1, l1 + r_1);
    hs[2] = fmaf(2.f, rv.vs2, l2 + r_2);
    hs[3] = fmaf(2.f, rv.vs3, l3 + r_3);
    hdR = rv.vs3 - rv.rt2;   // col w0+128 (valid on lane31)
}

__global__ __launch_bounds__(NT, 4)
void sobel_sign_kernel(const float* __restrict__ x,
                       float* __restrict__ y,
                       float* __restrict__ y0,
                       float* __restrict__ y1) {
    const int lane = threadIdx.x & 31;
    const int wid  = threadIdx.x >> 5;
    const int b    = blockIdx.z;
    const int w0   = blockIdx.x * 128;
    const int r0   = (blockIdx.y * NWARP + wid) * RS;
    const int col  = w0 + lane;

    const float* __restrict__ xb = x + (size_t)b * IMG_H * IMG_W + col;
    float* __restrict__ ybx = y + (size_t)b * 2 * IMG_H * IMG_W + col;
    float* __restrict__ yby = ybx + (size_t)IMG_H * IMG_W;
    float* __restrict__ y0b = y0 + (size_t)b * (IMG_H - 1) * (IMG_W - 1) + col;
    float* __restrict__ y1b = y1 + (size_t)b * (IMG_H - 1) * (IMG_W - 1) + col;

    const bool lane0  = (lane == 0);
    const bool lane31 = (lane == 31);
    const bool has_l  = (w0 > 0);
    const bool has_r  = (w0 + 128 < IMG_W);
    const bool skip3  = lane31 && !has_r;   // col w0+127 == 1023 on last strip

    float hdP1[4], hdP2[4], hsP1[4], hsP2[4];
    float hdRP1, hdRP2;
    float sgyP[4] = {0, 0, 0, 0};

    // ---- prologue: rows r0-1 and r0 ----
    {
        RowVals rv = load_row(xb, r0 - 1, lane0, lane31, has_l, has_r);
        row_combos(rv, lane0, lane31, hdP2, hsP2, hdRP2);
    }
    {
        RowVals rv = load_row(xb, r0, lane0, lane31, has_l, has_r);
        row_combos(rv, lane0, lane31, hdP1, hsP1, hdRP1);
    }

    // ---- main: emit y,y0 at m=r0+it ; y1 at m-1 (it>=1) ----
    #pragma unroll 4
    for (int it = 0; it < RS; it++) {
        const int j = r0 + 1 + it;
        RowVals rv = load_row(xb, j, lane0, lane31, has_l, has_r);
        float hd[4], hs[4], hdR;
        row_combos(rv, lane0, lane31, hd, hs, hdR);

        const int m = r0 + it;
        float gy[4], sgy[4], gx[4], sgx[4];
        #pragma unroll
        for (int k = 0; k < 4; k++) {
            gy[k]  = hsP2[k] - hs[k];
            sgy[k] = fsign(gy[k]);
            gx[k]  = fmaf(2.f, hdP1[k], hdP2[k] + hd[k]);
            sgx[k] = fsign(gx[k]);
        }
        const float gxR = fmaf(2.f, hdRP1, hdRP2 + hdR);

        const unsigned ro = (unsigned)m * IMG_W;
        ybx[ro +  0] = gx[0];  ybx[ro + 32] = gx[1];
        ybx[ro + 64] = gx[2];  ybx[ro + 96] = gx[3];
        yby[ro +  0] = gy[0];  yby[ro + 32] = gy[1];
        yby[ro + 64] = gy[2];  yby[ro + 96] = gy[3];

        // neighbor signs for y0
        float sxn0 = __shfl_down_sync(FULL, sgx[0], 1);
        float sxn1 = __shfl_down_sync(FULL, sgx[1], 1);
        float sxn2 = __shfl_down_sync(FULL, sgx[2], 1);
        float sxn3 = __shfl_down_sync(FULL, sgx[3], 1);
        const float nb0 = __shfl_sync(FULL, sgx[1], 0);
        const float nb1 = __shfl_sync(FULL, sgx[2], 0);
        const float nb2 = __shfl_sync(FULL, sgx[3], 0);
        if (lane31) { sxn0 = nb0; sxn1 = nb1; sxn2 = nb2; sxn3 = fsign(gxR); }

        if (m < IMG_H - 1) {
            const unsigned eo = (unsigned)m * (IMG_W - 1);
            y0b[eo +  0] = sgx[0] - sxn0;
            y0b[eo + 32] = sgx[1] - sxn1;
            y0b[eo + 64] = sgx[2] - sxn2;
            if (!skip3) y0b[eo + 96] = sgx[3] - sxn3;
        }
        if (it >= 1) {   // m-1 = r0+it-1 <= 1022 always here
            const unsigned eo = (unsigned)(m - 1) * (IMG_W - 1);
            y1b[eo +  0] = sgyP[0] - sgy[0];
            y1b[eo + 32] = sgyP[1] - sgy[1];
            y1b[eo + 64] = sgyP[2] - sgy[2];
            if (!skip3) y1b[eo + 96] = sgyP[3] - sgy[3];
        }
        #pragma unroll
        for (int k = 0; k < 4; k++) {
            sgyP[k] = sgy[k];
            hdP2[k] = hdP1[k]; hdP1[k] = hd[k];
            hsP2[k] = hsP1[k]; hsP1[k] = hs[k];
        }
        hdRP2 = hdRP1; hdRP1 = hdR;
    }

    // ---- epilogue: y1 row r0+RS-1 needs gy at row r0+RS ----
    // After the loop: hsP2 = hs(row r0+RS-1); gy(r0+RS) = hsP2 - hs(r0+RS+1).
    {
        const int m1 = r0 + RS - 1;
        if (m1 < IMG_H - 1) {
            RowVals rv = load_row(xb, r0 + RS + 1, lane0, lane31, has_l, has_r);
            float hd[4], hs[4], hdR;
            row_combos(rv, lane0, lane31, hd, hs, hdR);
            const unsigned eo = (unsigned)m1 * (IMG_W - 1);
            #pragma unroll
            for (int k = 0; k < 4; k++) {
                const float sgy = fsign(hsP2[k] - hs[k]);
                if (k < 3 || !skip3)
                    y1b[eo + 32u * k] = sgyP[k] - sgy;
            }
        }
    }
}

extern "C" void kernel_launch(void* const* d_in, const int* in_sizes, int n_in,
                              void* d_out, int out_size) {
    const float* x = (const float*)d_in[0];
    const int B = in_sizes[0] / (IMG_H * IMG_W);

    float* y  = (float*)d_out;
    float* y0 = y  + (size_t)B * 2 * IMG_H * IMG_W;
    float* y1 = y0 + (size_t)B * (IMG_H - 1) * (IMG_W - 1);

    dim3 block(NT, 1, 1);
    dim3 grid(IMG_W / 128, IMG_H / (RS * NWARP), B);
    sobel_sign_kernel<<<grid, block>>>(x, y, y0, y1);
}